// round 2
// baseline (speedup 1.0000x reference)
#include <cuda_runtime.h>

#define B_  16
#define C_  256
#define C2_ 128
#define N_  2048
#define BN_EPS 1e-5f

// ---------------- scratch (device globals; no allocation allowed) ----------
__device__ float g_Q [(size_t)B_ * C2_ * N_];           // 16 MB  [b][c2][n]
__device__ float g_Kp[(size_t)B_ * C2_ * N_];           // 16 MB  [b][c2][n]
__device__ float g_V [(size_t)B_ * C_  * N_];           // 32 MB  [b][c][n]
__device__ float g_X2[(size_t)B_ * C_  * N_];           // 32 MB  [b][c][n]
__device__ float g_E [(size_t)B_ * N_  * N_];           // 256 MB [b][n][m]
__device__ float g_D [(size_t)B_ * C_  * N_];           // 32 MB  [b][c][n]
__device__ float g_CS[(size_t)B_ * N_];                 // colsum [b][m]

// ---------------------------------------------------------------------------
// Generic 128x128 tiled SGEMM, K-tile 8, 256 threads, 8x8 microtile,
// double-buffered smem.  C[row,col] = sum_k A(row,k) * B(k,col)  per batch z.
//   ATRANS=false: A is [M,Kdim] row-major
//   ATRANS=true : A is [Kdim,M] row-major (used for E = Q^T K)
// Epilogues:
//   EPI 0: C = acc
//   EPI 1: C = acc + bias[row]
//   EPI 2: C = X2 - acc / (1e-9 + colsum[col])          (D = x2 - x_r)
//   EPI 3: C = relu((acc + bt[row])*inv[row] + shift[row]) + X2   (final out)
// ---------------------------------------------------------------------------
template<int EPI, bool ATRANS>
__global__ __launch_bounds__(256, 2)
void sgemm_k(const float* __restrict__ Ag, const float* __restrict__ Bg,
             float* __restrict__ Cg,
             int M, int Np, int Kdim,
             size_t aB, size_t bB, size_t cB,
             const float* __restrict__ bias,
             const float* __restrict__ x2g,
             const float* __restrict__ csg,
             const float* __restrict__ gga, const float* __restrict__ gbe,
             const float* __restrict__ gme, const float* __restrict__ gva,
             const float* __restrict__ gbt)
{
    __shared__ float As[2][8][128];
    __shared__ float Bs[2][8][128];

    const int bz = blockIdx.z;
    const float* A  = Ag + (size_t)bz * aB;
    const float* Bm = Bg + (size_t)bz * bB;
    float*       Cp = Cg + (size_t)bz * cB;

    const int mBase = blockIdx.y * 128;
    const int nBase = blockIdx.x * 128;
    const int tid = threadIdx.x;
    const int tx = tid & 15, ty = tid >> 4;

    int ar, ac;
    if (ATRANS) { ar = tid >> 5; ac = (tid & 31) * 4; }
    else        { ar = tid >> 1; ac = (tid & 1) * 4; }
    const int br = tid >> 5, bc = (tid & 31) * 4;

    float acc[8][8];
    #pragma unroll
    for (int i = 0; i < 8; i++)
        #pragma unroll
        for (int j = 0; j < 8; j++) acc[i][j] = 0.f;

    const int KT = Kdim >> 3;
    float4 aReg, bReg;

    // prologue: tile 0
    if (ATRANS) aReg = *(const float4*)(A + (size_t)ar * M + mBase + ac);
    else        aReg = *(const float4*)(A + (size_t)(mBase + ar) * Kdim + ac);
    bReg = *(const float4*)(Bm + (size_t)br * Np + nBase + bc);
    if (ATRANS) { *(float4*)&As[0][ar][ac] = aReg; }
    else {
        As[0][ac+0][ar] = aReg.x; As[0][ac+1][ar] = aReg.y;
        As[0][ac+2][ar] = aReg.z; As[0][ac+3][ar] = aReg.w;
    }
    *(float4*)&Bs[0][br][bc] = bReg;
    __syncthreads();

    int st = 0;
    for (int kt = 0; kt < KT; ++kt) {
        if (kt + 1 < KT) {
            const int k0 = (kt + 1) << 3;
            if (ATRANS) aReg = *(const float4*)(A + (size_t)(k0 + ar) * M + mBase + ac);
            else        aReg = *(const float4*)(A + (size_t)(mBase + ar) * Kdim + k0 + ac);
            bReg = *(const float4*)(Bm + (size_t)(k0 + br) * Np + nBase + bc);
        }
        #pragma unroll
        for (int k = 0; k < 8; k++) {
            float a[8], bb[8];
            *(float4*)&a[0]  = *(const float4*)&As[st][k][ty * 8];
            *(float4*)&a[4]  = *(const float4*)&As[st][k][ty * 8 + 4];
            *(float4*)&bb[0] = *(const float4*)&Bs[st][k][tx * 8];
            *(float4*)&bb[4] = *(const float4*)&Bs[st][k][tx * 8 + 4];
            #pragma unroll
            for (int i = 0; i < 8; i++)
                #pragma unroll
                for (int j = 0; j < 8; j++)
                    acc[i][j] = fmaf(a[i], bb[j], acc[i][j]);
        }
        if (kt + 1 < KT) {
            st ^= 1;
            if (ATRANS) { *(float4*)&As[st][ar][ac] = aReg; }
            else {
                As[st][ac+0][ar] = aReg.x; As[st][ac+1][ar] = aReg.y;
                As[st][ac+2][ar] = aReg.z; As[st][ac+3][ar] = aReg.w;
            }
            *(float4*)&Bs[st][br][bc] = bReg;
            __syncthreads();
        }
    }

    const int row0 = mBase + ty * 8;
    const int col0 = nBase + tx * 8;

    if (EPI == 0 || EPI == 1) {
        #pragma unroll
        for (int i = 0; i < 8; i++) {
            float bb = (EPI == 1) ? bias[row0 + i] : 0.f;
            float4 o0 = make_float4(acc[i][0]+bb, acc[i][1]+bb, acc[i][2]+bb, acc[i][3]+bb);
            float4 o1 = make_float4(acc[i][4]+bb, acc[i][5]+bb, acc[i][6]+bb, acc[i][7]+bb);
            size_t off = (size_t)(row0 + i) * Np + col0;
            *(float4*)(Cp + off)     = o0;
            *(float4*)(Cp + off + 4) = o1;
        }
    } else if (EPI == 2) {
        const float* X2 = x2g + (size_t)bz * cB;
        const float* cs = csg + (size_t)bz * Np;
        float inv[8];
        #pragma unroll
        for (int j = 0; j < 8; j++) inv[j] = 1.f / (1e-9f + cs[col0 + j]);
        #pragma unroll
        for (int i = 0; i < 8; i++) {
            size_t off = (size_t)(row0 + i) * Np + col0;
            float4 x0 = *(const float4*)(X2 + off);
            float4 x1 = *(const float4*)(X2 + off + 4);
            float4 o0 = make_float4(x0.x - acc[i][0]*inv[0], x0.y - acc[i][1]*inv[1],
                                    x0.z - acc[i][2]*inv[2], x0.w - acc[i][3]*inv[3]);
            float4 o1 = make_float4(x1.x - acc[i][4]*inv[4], x1.y - acc[i][5]*inv[5],
                                    x1.z - acc[i][6]*inv[6], x1.w - acc[i][7]*inv[7]);
            *(float4*)(Cp + off)     = o0;
            *(float4*)(Cp + off + 4) = o1;
        }
    } else { // EPI == 3
        const float* X2 = x2g + (size_t)bz * cB;
        #pragma unroll
        for (int i = 0; i < 8; i++) {
            const int r = row0 + i;
            const float iv = gga[r] * rsqrtf(gva[r] + BN_EPS);
            const float sh = gbe[r] - gme[r] * iv;
            const float bo = gbt[r];
            size_t off = (size_t)r * Np + col0;
            float4 x0 = *(const float4*)(X2 + off);
            float4 x1 = *(const float4*)(X2 + off + 4);
            float4 o0, o1;
            o0.x = fmaxf((acc[i][0]+bo)*iv + sh, 0.f) + x0.x;
            o0.y = fmaxf((acc[i][1]+bo)*iv + sh, 0.f) + x0.y;
            o0.z = fmaxf((acc[i][2]+bo)*iv + sh, 0.f) + x0.z;
            o0.w = fmaxf((acc[i][3]+bo)*iv + sh, 0.f) + x0.w;
            o1.x = fmaxf((acc[i][4]+bo)*iv + sh, 0.f) + x1.x;
            o1.y = fmaxf((acc[i][5]+bo)*iv + sh, 0.f) + x1.y;
            o1.z = fmaxf((acc[i][6]+bo)*iv + sh, 0.f) + x1.z;
            o1.w = fmaxf((acc[i][7]+bo)*iv + sh, 0.f) + x1.w;
            *(float4*)(Cp + off)     = o0;
            *(float4*)(Cp + off + 4) = o1;
        }
    }
}

// ---------------------------------------------------------------------------
// Row softmax in-place: one block per (b, n) row of 2048 fp32 (registers).
// ---------------------------------------------------------------------------
__global__ __launch_bounds__(256)
void softmax_k(float* __restrict__ E)
{
    __shared__ float redm[8];
    __shared__ float reds[8];
    const size_t row = blockIdx.x;
    float4* p = reinterpret_cast<float4*>(E + row * (size_t)N_);
    const int tid = threadIdx.x;

    float4 v0 = p[tid];
    float4 v1 = p[tid + 256];

    float mx = fmaxf(fmaxf(fmaxf(v0.x, v0.y), fmaxf(v0.z, v0.w)),
                     fmaxf(fmaxf(v1.x, v1.y), fmaxf(v1.z, v1.w)));
    #pragma unroll
    for (int o = 16; o > 0; o >>= 1)
        mx = fmaxf(mx, __shfl_xor_sync(0xffffffffu, mx, o));
    if ((tid & 31) == 0) redm[tid >> 5] = mx;
    __syncthreads();
    mx = fmaxf(fmaxf(fmaxf(redm[0], redm[1]), fmaxf(redm[2], redm[3])),
               fmaxf(fmaxf(redm[4], redm[5]), fmaxf(redm[6], redm[7])));

    v0.x = __expf(v0.x - mx); v0.y = __expf(v0.y - mx);
    v0.z = __expf(v0.z - mx); v0.w = __expf(v0.w - mx);
    v1.x = __expf(v1.x - mx); v1.y = __expf(v1.y - mx);
    v1.z = __expf(v1.z - mx); v1.w = __expf(v1.w - mx);

    float s = (v0.x + v0.y + v0.z + v0.w) + (v1.x + v1.y + v1.z + v1.w);
    #pragma unroll
    for (int o = 16; o > 0; o >>= 1)
        s += __shfl_xor_sync(0xffffffffu, s, o);
    if ((tid & 31) == 0) reds[tid >> 5] = s;
    __syncthreads();
    s = (reds[0] + reds[1] + reds[2] + reds[3]) +
        (reds[4] + reds[5] + reds[6] + reds[7]);

    const float inv = 1.f / s;
    v0.x *= inv; v0.y *= inv; v0.z *= inv; v0.w *= inv;
    v1.x *= inv; v1.y *= inv; v1.z *= inv; v1.w *= inv;
    p[tid]       = v0;
    p[tid + 256] = v1;
}

__global__ void zero_k(float* __restrict__ p, int n)
{
    int i = blockIdx.x * blockDim.x + threadIdx.x;
    if (i < n) p[i] = 0.f;
}

// colsum[b][m] += sum over a 128-row chunk of S[b][n][m]
__global__ __launch_bounds__(256)
void colsum_k(const float* __restrict__ S, float* __restrict__ cs)
{
    const int b  = blockIdx.z;
    const int m  = blockIdx.x * 256 + threadIdx.x;
    const int n0 = blockIdx.y * 128;
    const float* p = S + (size_t)b * N_ * N_ + (size_t)n0 * N_ + m;
    float s0 = 0.f, s1 = 0.f, s2 = 0.f, s3 = 0.f;
    #pragma unroll 4
    for (int n = 0; n < 128; n += 4) {
        s0 += p[(size_t)(n + 0) * N_];
        s1 += p[(size_t)(n + 1) * N_];
        s2 += p[(size_t)(n + 2) * N_];
        s3 += p[(size_t)(n + 3) * N_];
    }
    atomicAdd(&cs[b * N_ + m], (s0 + s1) + (s2 + s3));
}

// ---------------------------------------------------------------------------
extern "C" void kernel_launch(void* const* d_in, const int* in_sizes, int n_in,
                              void* d_out, int out_size)
{
    const float* q  = (const float*)d_in[0];
    const float* x  = (const float*)d_in[1];
    const float* Wq = (const float*)d_in[2];
    const float* Wk = (const float*)d_in[3];
    const float* Wv = (const float*)d_in[4];
    const float* bv = (const float*)d_in[5];
    const float* Wt = (const float*)d_in[6];
    const float* bt = (const float*)d_in[7];
    const float* ga = (const float*)d_in[8];
    const float* be = (const float*)d_in[9];
    const float* rm = (const float*)d_in[10];
    const float* rv = (const float*)d_in[11];
    float* out = (float*)d_out;

    float *pQ, *pK, *pV, *pX2, *pE, *pD, *pCS;
    cudaGetSymbolAddress((void**)&pQ,  g_Q);
    cudaGetSymbolAddress((void**)&pK,  g_Kp);
    cudaGetSymbolAddress((void**)&pV,  g_V);
    cudaGetSymbolAddress((void**)&pX2, g_X2);
    cudaGetSymbolAddress((void**)&pE,  g_E);
    cudaGetSymbolAddress((void**)&pD,  g_D);
    cudaGetSymbolAddress((void**)&pCS, g_CS);

    const size_t s2 = (size_t)C2_ * N_;   // 128*2048
    const size_t sc = (size_t)C_  * N_;   // 256*2048
    const size_t se = (size_t)N_  * N_;   // 2048*2048
    dim3 blk(256);

    // Q = Wq @ q[b]            [128,2048]
    sgemm_k<0,false><<<dim3(16,1,B_), blk>>>(Wq, q, pQ, C2_, N_, C2_,
        0, s2, s2, nullptr, nullptr, nullptr, nullptr, nullptr, nullptr, nullptr, nullptr);
    // K = Wk @ x[b]            [128,2048]
    sgemm_k<0,false><<<dim3(16,1,B_), blk>>>(Wk, x, pK, C2_, N_, C2_,
        0, s2, s2, nullptr, nullptr, nullptr, nullptr, nullptr, nullptr, nullptr, nullptr);
    // V = Wv @ q[b] + bv       [256,2048]
    sgemm_k<1,false><<<dim3(16,2,B_), blk>>>(Wv, q, pV, C_, N_, C2_,
        0, s2, sc, bv, nullptr, nullptr, nullptr, nullptr, nullptr, nullptr, nullptr);
    // X2 = Wv @ x[b] + bv      [256,2048]
    sgemm_k<1,false><<<dim3(16,2,B_), blk>>>(Wv, x, pX2, C_, N_, C2_,
        0, s2, sc, bv, nullptr, nullptr, nullptr, nullptr, nullptr, nullptr, nullptr);
    // E = Q^T K                [2048,2048] per batch
    sgemm_k<0,true><<<dim3(16,16,B_), blk>>>(pQ, pK, pE, N_, N_, C2_,
        s2, s2, se, nullptr, nullptr, nullptr, nullptr, nullptr, nullptr, nullptr, nullptr);
    // row softmax in-place
    softmax_k<<<B_ * N_, 256>>>(pE);
    // column sums
    zero_k<<<(B_ * N_ + 255) / 256, 256>>>(pCS, B_ * N_);
    colsum_k<<<dim3(N_ / 256, 16, B_), 256>>>(pE, pCS);
    // D = X2 - (V @ S) / (1e-9 + colsum)
    sgemm_k<2,false><<<dim3(16,2,B_), blk>>>(pV, pE, pD, C_, N_, N_,
        sc, se, sc, nullptr, pX2, pCS, nullptr, nullptr, nullptr, nullptr, nullptr);
    // out = relu(bn(Wt @ D + bt)) + X2
    sgemm_k<3,false><<<dim3(16,2,B_), blk>>>(Wt, pD, out, C_, N_, C_,
        0, sc, sc, nullptr, pX2, nullptr, ga, be, rm, rv, bt);
}